// round 2
// baseline (speedup 1.0000x reference)
#include <cuda_runtime.h>
#include <cuda_bf16.h>
#include <math.h>

// Problem: x [B=8, C=3, T=512, H=64, W=64] fp32 -> out [B=8, T=512] fp32
// out[b] = Vt[1] * explained_variance[1] of PCA.fit(xm[b]) where xm = mean over (H,W).
//
// Math: Xc = X - colmean (center over C). Columns of Xc sum to 0 -> w=(1,1,1)/sqrt(3)
// is a null vector of G = Xc Xc^T (3x3). Project G onto basis
// e1=(1,-1,0)/sqrt2, e2=(1,1,-2)/sqrt6 (both _|_ w) -> 2x2 H. Closed-form eigen.
// lambda1 = smaller eig of H (second-largest of G). u1 = eigvec, sign per svd_flip.
// out[t] = sign * sqrt(lambda1)/2 * (Xc^T u1)[t].

#define B 8
#define C 3
#define T 512
#define HW 4096
#define NROWS (B * C * T)   // 12288

__device__ float g_xm[NROWS];   // spatial means, [B][C][T]

// ---------------------------------------------------------------------------
// Kernel 1: mean over H*W (4096 contiguous floats) per row. One block per row.
// 256 threads x 4 float4 = 4096 floats. HBM-streaming bound.
// 4 independent accumulators -> 4 outstanding LDG.128 per thread (MLP).
// ---------------------------------------------------------------------------
__global__ void __launch_bounds__(256) reduce_hw_kernel(const float* __restrict__ x) {
    const int row = blockIdx.x;
    const float4* __restrict__ p =
        reinterpret_cast<const float4*>(x + (size_t)row * HW);
    const int tid = threadIdx.x;

    float4 v0 = __ldg(&p[tid]);
    float4 v1 = __ldg(&p[tid + 256]);
    float4 v2 = __ldg(&p[tid + 512]);
    float4 v3 = __ldg(&p[tid + 768]);

    float s0 = (v0.x + v0.y) + (v0.z + v0.w);
    float s1 = (v1.x + v1.y) + (v1.z + v1.w);
    float s2 = (v2.x + v2.y) + (v2.z + v2.w);
    float s3 = (v3.x + v3.y) + (v3.z + v3.w);
    float s = (s0 + s1) + (s2 + s3);

    // warp tree reduce
#pragma unroll
    for (int o = 16; o > 0; o >>= 1) s += __shfl_xor_sync(0xffffffffu, s, o);

    __shared__ float ws[8];
    if ((tid & 31) == 0) ws[tid >> 5] = s;
    __syncthreads();
    if (tid == 0) {
        float v = ws[0];
#pragma unroll
        for (int k = 1; k < 8; k++) v += ws[k];
        g_xm[row] = v * (1.0f / (float)HW);
    }
}

// ---------------------------------------------------------------------------
// Kernel 2: one block per batch (512 threads, one per t).
// Build G (6 unique entries) by deterministic tree reduction, eigen-solve in
// double on thread 0, broadcast, project and write.
// ---------------------------------------------------------------------------
__global__ void __launch_bounds__(512) pca_kernel(float* __restrict__ out) {
    const int b = blockIdx.x;
    const int t = threadIdx.x;           // 0..511
    const float* __restrict__ X = g_xm + b * (C * T);

    const float x0 = X[t];
    const float x1 = X[T + t];
    const float x2 = X[2 * T + t];
    const float m  = (x0 + x1 + x2) * (1.0f / 3.0f);
    const float c0 = x0 - m, c1 = x1 - m, c2 = x2 - m;

    float g[6];
    g[0] = c0 * c0;   // G00
    g[1] = c0 * c1;   // G01
    g[2] = c0 * c2;   // G02
    g[3] = c1 * c1;   // G11
    g[4] = c1 * c2;   // G12
    g[5] = c2 * c2;   // G22

    // warp reduce each of the 6 partials
#pragma unroll
    for (int k = 0; k < 6; k++) {
#pragma unroll
        for (int o = 16; o > 0; o >>= 1)
            g[k] += __shfl_xor_sync(0xffffffffu, g[k], o);
    }

    __shared__ float red[6][16];         // 16 warps
    const int warp = t >> 5;
    if ((t & 31) == 0) {
#pragma unroll
        for (int k = 0; k < 6; k++) red[k][warp] = g[k];
    }
    __syncthreads();

    __shared__ float sh_u[3];
    __shared__ float sh_scale;

    if (t == 0) {
        double G00 = 0, G01 = 0, G02 = 0, G11 = 0, G12 = 0, G22 = 0;
        for (int k = 0; k < 16; k++) {
            G00 += (double)red[0][k];
            G01 += (double)red[1][k];
            G02 += (double)red[2][k];
            G11 += (double)red[3][k];
            G12 += (double)red[4][k];
            G22 += (double)red[5][k];
        }
        // Basis orthogonal to (1,1,1):
        //   b1 = a*(1,-1,0),  a = 1/sqrt(2)
        //   b2 = d*(1,1,-2),  d = 1/sqrt(6)
        const double a = 0.70710678118654752440;   // 1/sqrt(2)
        const double d = 0.40824829046386301637;   // 1/sqrt(6)
        const double H11 = a * a * (G00 - 2.0 * G01 + G11);
        const double H12 = a * d * (G00 - G11 - 2.0 * G02 + 2.0 * G12);
        const double H22 = d * d * (G00 + 2.0 * G01 + G11
                                    - 4.0 * G02 - 4.0 * G12 + 4.0 * G22);

        const double mid  = 0.5 * (H11 + H22);
        const double diff = 0.5 * (H11 - H22);
        const double rad  = sqrt(diff * diff + H12 * H12);
        double lam1 = mid - rad;                   // second-largest eig of G
        if (lam1 < 0.0) lam1 = 0.0;

        // eigenvector of H for lam1 (pick the better-conditioned residual form)
        double v0a = H12,        v1a = lam1 - H11;
        double v0b = lam1 - H22, v1b = H12;
        double na = v0a * v0a + v1a * v1a;
        double nb = v0b * v0b + v1b * v1b;
        double v0 = (na >= nb) ? v0a : v0b;
        double v1 = (na >= nb) ? v1a : v1b;
        double nn = sqrt(v0 * v0 + v1 * v1);
        if (nn < 1e-300) { v0 = 1.0; v1 = 0.0; nn = 1.0; }
        v0 /= nn; v1 /= nn;

        // back to 3D (unit, since b1,b2 orthonormal)
        double u0 = a * v0 + d * v1;
        double u1v = -a * v0 + d * v1;
        double u2 = -2.0 * d * v1;

        // svd_flip sign: sign of the max-|.| component (first occurrence)
        double au0 = fabs(u0), au1 = fabs(u1v), au2 = fabs(u2);
        double pick = u0;
        double best = au0;
        if (au1 > best) { best = au1; pick = u1v; }
        if (au2 > best) { best = au2; pick = u2; }
        double s = (pick < 0.0) ? -1.0 : 1.0;     // sign(0) -> +1

        double scale = s * 0.5 * sqrt(lam1);      // S1/2 with sign

        sh_u[0] = (float)u0;
        sh_u[1] = (float)u1v;
        sh_u[2] = (float)u2;
        sh_scale = (float)scale;
    }
    __syncthreads();

    const float sc = sh_scale;
    out[b * T + t] = sc * (c0 * sh_u[0] + c1 * sh_u[1] + c2 * sh_u[2]);
}

extern "C" void kernel_launch(void* const* d_in, const int* in_sizes, int n_in,
                              void* d_out, int out_size) {
    const float* x = (const float*)d_in[0];
    float* out = (float*)d_out;
    (void)in_sizes; (void)n_in; (void)out_size;

    reduce_hw_kernel<<<NROWS, 256>>>(x);
    pca_kernel<<<B, 512>>>(out);
}

// round 3
// speedup vs baseline: 1.2302x; 1.2302x over previous
#include <cuda_runtime.h>
#include <cuda_bf16.h>
#include <math.h>

// Problem: x [B=8, C=3, T=512, H=64, W=64] fp32 -> out [B=8, T=512] fp32
// out[b] = Vt[1] * explained_variance[1] of PCA.fit(xm[b]) where xm = mean over (H,W).
//
// Math: Xc = X - colmean (center over C). Columns of Xc sum to 0 -> w=(1,1,1)/sqrt(3)
// is a null vector of G = Xc Xc^T (3x3). Project G onto basis
// e1=(1,-1,0)/sqrt2, e2=(1,1,-2)/sqrt6 (both _|_ w) -> 2x2 H. Closed-form eigen.
// lambda1 = smaller eig of H (second-largest of G). u1 = eigvec, sign per svd_flip.
// out[t] = sign * sqrt(lambda1)/2 * (Xc^T u1)[t].

#define B 8
#define C 3
#define T 512
#define HW 4096
#define NROWS (B * C * T)   // 12288

__device__ float g_xm[NROWS];   // spatial means, [B][C][T]

// ---------------------------------------------------------------------------
// Kernel 1: mean over H*W (4096 contiguous floats) per row. One block per row.
// 256 threads x 4 float4 = 4096 floats. At HBM roofline (~6.9 TB/s measured).
// ---------------------------------------------------------------------------
__global__ void __launch_bounds__(256) reduce_hw_kernel(const float* __restrict__ x) {
    const int row = blockIdx.x;
    const float4* __restrict__ p =
        reinterpret_cast<const float4*>(x + (size_t)row * HW);
    const int tid = threadIdx.x;

    float4 v0 = __ldg(&p[tid]);
    float4 v1 = __ldg(&p[tid + 256]);
    float4 v2 = __ldg(&p[tid + 512]);
    float4 v3 = __ldg(&p[tid + 768]);

    float s0 = (v0.x + v0.y) + (v0.z + v0.w);
    float s1 = (v1.x + v1.y) + (v1.z + v1.w);
    float s2 = (v2.x + v2.y) + (v2.z + v2.w);
    float s3 = (v3.x + v3.y) + (v3.z + v3.w);
    float s = (s0 + s1) + (s2 + s3);

#pragma unroll
    for (int o = 16; o > 0; o >>= 1) s += __shfl_xor_sync(0xffffffffu, s, o);

    __shared__ float ws[8];
    if ((tid & 31) == 0) ws[tid >> 5] = s;
    __syncthreads();
    if (tid == 0) {
        float v = ws[0];
#pragma unroll
        for (int k = 1; k < 8; k++) v += ws[k];
        g_xm[row] = v * (1.0f / (float)HW);
    }
}

// ---------------------------------------------------------------------------
// Kernel 2: one block per batch (512 threads, one per t). ALL FP32.
// Build G (6 entries) via warp shuffles + warp-0 cross-warp shuffle reduce,
// closed-form 2x2 eigen in float on thread 0, broadcast, project, write.
// ---------------------------------------------------------------------------
__global__ void __launch_bounds__(512) pca_kernel(float* __restrict__ out) {
    const int b = blockIdx.x;
    const int t = threadIdx.x;           // 0..511
    const float* __restrict__ X = g_xm + b * (C * T);

    const float x0 = X[t];
    const float x1 = X[T + t];
    const float x2 = X[2 * T + t];
    const float m  = (x0 + x1 + x2) * (1.0f / 3.0f);
    const float c0 = x0 - m, c1 = x1 - m, c2 = x2 - m;

    float g[6];
    g[0] = c0 * c0;   // G00
    g[1] = c0 * c1;   // G01
    g[2] = c0 * c2;   // G02
    g[3] = c1 * c1;   // G11
    g[4] = c1 * c2;   // G12
    g[5] = c2 * c2;   // G22

    // intra-warp reduce
#pragma unroll
    for (int k = 0; k < 6; k++) {
#pragma unroll
        for (int o = 16; o > 0; o >>= 1)
            g[k] += __shfl_xor_sync(0xffffffffu, g[k], o);
    }

    __shared__ float red[16][8];         // 16 warps x 6 entries (padded)
    const int warp = t >> 5;
    if ((t & 31) == 0) {
#pragma unroll
        for (int k = 0; k < 6; k++) red[warp][k] = g[k];
    }
    __syncthreads();

    __shared__ float sh_u[3];
    __shared__ float sh_scale;

    // warp 0: cross-warp reduce 16 partials per entry via shuffles
    if (warp == 0) {
        const int lane = t;              // 0..31
        float G[6];
#pragma unroll
        for (int k = 0; k < 6; k++) {
            float v = (lane < 16) ? red[lane][k] : 0.0f;
#pragma unroll
            for (int o = 8; o > 0; o >>= 1)
                v += __shfl_xor_sync(0xffffffffu, v, o);
            G[k] = v;                    // valid on all lanes; use lane 0
        }

        if (lane == 0) {
            const float G00 = G[0], G01 = G[1], G02 = G[2];
            const float G11 = G[3], G12 = G[4], G22 = G[5];
            // Basis orthogonal to (1,1,1):
            //   b1 = a*(1,-1,0),  a = 1/sqrt(2)
            //   b2 = d*(1,1,-2),  d = 1/sqrt(6)
            const float a = 0.70710678f;
            const float d = 0.40824829f;
            const float H11 = a * a * (G00 - 2.0f * G01 + G11);
            const float H12 = a * d * (G00 - G11 - 2.0f * G02 + 2.0f * G12);
            const float H22 = d * d * (G00 + 2.0f * G01 + G11
                                       - 4.0f * G02 - 4.0f * G12 + 4.0f * G22);

            const float mid  = 0.5f * (H11 + H22);
            const float diff = 0.5f * (H11 - H22);
            const float rad  = sqrtf(diff * diff + H12 * H12);
            float lam1 = mid - rad;                // second-largest eig of G
            if (lam1 < 0.0f) lam1 = 0.0f;

            // eigenvector of H for lam1 (better-conditioned residual form)
            float v0a = H12,        v1a = lam1 - H11;
            float v0b = lam1 - H22, v1b = H12;
            float na = v0a * v0a + v1a * v1a;
            float nb = v0b * v0b + v1b * v1b;
            float v0 = (na >= nb) ? v0a : v0b;
            float v1 = (na >= nb) ? v1a : v1b;
            float nn2 = v0 * v0 + v1 * v1;
            if (nn2 < 1e-30f) { v0 = 1.0f; v1 = 0.0f; nn2 = 1.0f; }
            const float rinv = rsqrtf(nn2);
            v0 *= rinv; v1 *= rinv;

            // back to 3D (unit, since b1,b2 orthonormal)
            float u0  = a * v0 + d * v1;
            float u1v = -a * v0 + d * v1;
            float u2  = -2.0f * d * v1;

            // svd_flip sign: sign of the max-|.| component (first occurrence)
            float au0 = fabsf(u0), au1 = fabsf(u1v), au2 = fabsf(u2);
            float pick = u0;
            float best = au0;
            if (au1 > best) { best = au1; pick = u1v; }
            if (au2 > best) { best = au2; pick = u2; }
            const float s = (pick < 0.0f) ? -1.0f : 1.0f;   // sign(0) -> +1

            sh_u[0] = u0;
            sh_u[1] = u1v;
            sh_u[2] = u2;
            sh_scale = s * 0.5f * sqrtf(lam1);              // S1/2 with sign
        }
    }
    __syncthreads();

    const float sc = sh_scale;
    out[b * T + t] = sc * (c0 * sh_u[0] + c1 * sh_u[1] + c2 * sh_u[2]);
}

extern "C" void kernel_launch(void* const* d_in, const int* in_sizes, int n_in,
                              void* d_out, int out_size) {
    const float* x = (const float*)d_in[0];
    float* out = (float*)d_out;
    (void)in_sizes; (void)n_in; (void)out_size;

    reduce_hw_kernel<<<NROWS, 256>>>(x);
    pca_kernel<<<B, 512>>>(out);
}